// round 5
// baseline (speedup 1.0000x reference)
#include <cuda_runtime.h>
#include <cuda_bf16.h>
#include <math.h>

// Problem constants (fixed by the dataset): P=256, K=64, N derived from in_sizes.
#define PP 256
#define KK 64
#define TILE_M 128          // rows per CTA
#define XSTRIDE 264         // padded bf16 row stride for X tile (bank-conflict-free)
#define MSTRIDE 264         // padded bf16 row stride for mu tile
#define MAX_BLOCKS 8192

__device__ float         g_kap[KK];
__device__ float         g_w[KK];
__device__ __nv_bfloat16 g_mub[KK * PP];     // [k][p], p contiguous
__device__ float         g_partial[MAX_BLOCKS];

// ---------------------------------------------------------------------------
// Preprocess: norms, softplus, Kummer series, log-softmax(pi), bf16 mu_unit.
// ---------------------------------------------------------------------------
__global__ void prep_kernel(const float* __restrict__ mu,
                            const float* __restrict__ kappa,
                            const float* __restrict__ pi) {
    __shared__ float  srn[KK];
    __shared__ double s_lse_pi;
    int t = threadIdx.x;

    double logC = 0.0;
    if (t < KK) {
        // column norm of mu[:, t]  (mu is (P,K) row-major)
        double s = 0.0;
        for (int p = 0; p < PP; p++) {
            double v = (double)mu[p * KK + t];
            s += v * v;
        }
        srn[t] = (float)(1.0 / sqrt(s));

        // softplus(kappa)
        double x = (double)kappa[t];
        double kap = (x > 0.0) ? x + log1p(exp(-x)) : log1p(exp(x));
        g_kap[t] = (float)kap;

        // Kummer log-series  M(0.5, 128, kap)
        double lkap = log(kap);
        double foo = 0.0, logkum = 0.0;
        for (int j = 1; j <= 200; j++) {
            double jd = (double)j;
            foo += log((0.5 + jd - 1.0) / (jd * (128.0 + jd - 1.0))) + lkap;
            double mx = fmax(logkum, foo);
            double nl = mx + log1p(exp(-fabs(logkum - foo)));
            double d  = fabs(nl - logkum);
            logkum = nl;
            if (d < 1e-14) break;
        }
        double logSA = lgamma(128.0) - log(2.0) - 128.0 * log(M_PI);
        logC = logSA - logkum;
    }

    if (t == 0) {
        double m = -1e300;
        for (int k = 0; k < KK; k++) m = fmax(m, (double)pi[k]);
        double s = 0.0;
        for (int k = 0; k < KK; k++) s += exp((double)pi[k] - m);
        s_lse_pi = m + log(s);
    }
    __syncthreads();

    if (t < KK) {
        g_w[t] = (float)(logC + (double)pi[t] - s_lse_pi);
    }

    // mu_unit -> bf16, layout [k][p] contiguous in p
    for (int i = t; i < KK * PP; i += blockDim.x) {
        int k = i >> 8;        // /PP
        int p = i & 255;       // %PP
        g_mub[i] = __float2bfloat16(mu[p * KK + k] * srn[k]);
    }
}

// ---------------------------------------------------------------------------
// Main: 128-row tile GEMM (bf16 HMMA) + fused logsumexp epilogue.
// Each CTA may process several tiles (grid-stride over tiles) so the grid
// stays <= MAX_BLOCKS partials.
// ---------------------------------------------------------------------------
__global__ void __launch_bounds__(256) watson_main_kernel(
        const float* __restrict__ X, int Nrows, int ntiles) {
    extern __shared__ unsigned char smem_raw[];
    __nv_bfloat16* Xs = (__nv_bfloat16*)smem_raw;                 // 128 x 264
    __nv_bfloat16* Ms = Xs + TILE_M * XSTRIDE;                    // 64 x 264
    float* ws   = (float*)(Ms + KK * MSTRIDE);                    // 64
    float* ks   = ws + KK;                                        // 64
    float* wsum = ks + KK;                                        // 8

    const int tid = threadIdx.x;

    // stage mu (bf16), w, kap  (once per CTA)
    for (int i = tid; i < KK * PP; i += 256) {
        Ms[(i >> 8) * MSTRIDE + (i & 255)] = g_mub[i];
    }
    if (tid < KK) { ws[tid] = g_w[tid]; ks[tid] = g_kap[tid]; }

    const int warp = tid >> 5;
    const int lane = tid & 31;
    const int g = lane >> 2;   // groupID (row within 8)
    const int q = lane & 3;    // thread-in-group

    float block_acc = 0.f;

    for (int tile = blockIdx.x; tile < ntiles; tile += gridDim.x) {
        const long tile0 = (long)tile * TILE_M;
        const float4* X4 = (const float4*)X;
        const bool full_tile = (tile0 + TILE_M) <= (long)Nrows;

        __syncthreads();   // previous iteration's ldmatrix reads done

        if (full_tile) {
#pragma unroll 4
            for (int i = tid; i < TILE_M * (PP / 4); i += 256) {
                int r  = i >> 6;
                int c4 = i & 63;
                float4 v = X4[(tile0 + r) * (PP / 4) + c4];
                __nv_bfloat162* dst = (__nv_bfloat162*)(Xs + r * XSTRIDE + c4 * 4);
                dst[0] = __floats2bfloat162_rn(v.x, v.y);
                dst[1] = __floats2bfloat162_rn(v.z, v.w);
            }
        } else {
            for (int i = tid; i < TILE_M * (PP / 4); i += 256) {
                int r  = i >> 6;
                int c4 = i & 63;
                long grow = tile0 + r;
                float4 v = make_float4(0.f, 0.f, 0.f, 0.f);
                if (grow < (long)Nrows) v = X4[grow * (PP / 4) + c4];
                __nv_bfloat162* dst = (__nv_bfloat162*)(Xs + r * XSTRIDE + c4 * 4);
                dst[0] = __floats2bfloat162_rn(v.x, v.y);
                dst[1] = __floats2bfloat162_rn(v.z, v.w);
            }
        }
        __syncthreads();

        float acc[8][4];
#pragma unroll
        for (int nb = 0; nb < 8; nb++)
#pragma unroll
            for (int e = 0; e < 4; e++) acc[nb][e] = 0.f;

        // ldmatrix base: lane -> (row = lane%16, 8-col block = lane/16)
        unsigned a_addr0 = (unsigned)__cvta_generic_to_shared(
            Xs + (warp * 16 + (lane & 15)) * XSTRIDE + (lane >> 4) * 8);

#pragma unroll
        for (int ksi = 0; ksi < 16; ksi++) {
            unsigned a_addr = a_addr0 + (unsigned)(ksi * 16 * 2);
            unsigned a0, a1, a2, a3;
            asm volatile(
                "ldmatrix.sync.aligned.m8n8.x4.shared.b16 {%0,%1,%2,%3}, [%4];"
                : "=r"(a0), "=r"(a1), "=r"(a2), "=r"(a3) : "r"(a_addr));

#pragma unroll
            for (int nb = 0; nb < 8; nb++) {
                const __nv_bfloat16* bp = Ms + (nb * 8 + g) * MSTRIDE + ksi * 16 + 2 * q;
                unsigned b0 = *(const unsigned*)bp;
                unsigned b1 = *(const unsigned*)(bp + 8);
                asm volatile(
                    "mma.sync.aligned.m16n8k16.row.col.f32.bf16.bf16.f32 "
                    "{%0,%1,%2,%3}, {%4,%5,%6,%7}, {%8,%9}, {%0,%1,%2,%3};"
                    : "+f"(acc[nb][0]), "+f"(acc[nb][1]),
                      "+f"(acc[nb][2]), "+f"(acc[nb][3])
                    : "r"(a0), "r"(a1), "r"(a2), "r"(a3), "r"(b0), "r"(b1));
            }
        }

        // Epilogue: density = w[k] + kap[k]*proj^2 ; logsumexp over K per row.
        float rowsum = 0.f;
#pragma unroll
        for (int rh = 0; rh < 2; rh++) {
            long grow = tile0 + warp * 16 + g + rh * 8;
            float d[16];
            float m = -INFINITY;
#pragma unroll
            for (int nb = 0; nb < 8; nb++) {
#pragma unroll
                for (int e = 0; e < 2; e++) {
                    int comp = nb * 8 + 2 * q + e;
                    float pr = acc[nb][rh * 2 + e];
                    float dv = ws[comp] + ks[comp] * pr * pr;
                    d[nb * 2 + e] = dv;
                    m = fmaxf(m, dv);
                }
            }
            m = fmaxf(m, __shfl_xor_sync(0xffffffffu, m, 1));
            m = fmaxf(m, __shfl_xor_sync(0xffffffffu, m, 2));
            float s = 0.f;
#pragma unroll
            for (int i = 0; i < 16; i++) s += expf(d[i] - m);
            s += __shfl_xor_sync(0xffffffffu, s, 1);
            s += __shfl_xor_sync(0xffffffffu, s, 2);
            float L = m + logf(s);
            if (q == 0 && grow < (long)Nrows) rowsum += L;
        }

        // warp reduction, accumulate per-CTA
#pragma unroll
        for (int off = 16; off > 0; off >>= 1)
            rowsum += __shfl_xor_sync(0xffffffffu, rowsum, off);
        if (lane == 0) wsum[warp] = rowsum;
        __syncthreads();
        if (tid == 0) {
            float t = 0.f;
            for (int w = 0; w < 8; w++) t += wsum[w];
            block_acc += t;
        }
    }

    if (tid == 0) g_partial[blockIdx.x] = block_acc;
}

// ---------------------------------------------------------------------------
// Deterministic final reduction.
// ---------------------------------------------------------------------------
__global__ void reduce_kernel(float* __restrict__ out, int nblocks) {
    __shared__ double sd[256];
    double s = 0.0;
    for (int i = threadIdx.x; i < nblocks; i += 256) s += (double)g_partial[i];
    sd[threadIdx.x] = s;
    __syncthreads();
    for (int off = 128; off > 0; off >>= 1) {
        if (threadIdx.x < off) sd[threadIdx.x] += sd[threadIdx.x + off];
        __syncthreads();
    }
    if (threadIdx.x == 0) out[0] = (float)sd[0];
}

// ---------------------------------------------------------------------------
extern "C" void kernel_launch(void* const* d_in, const int* in_sizes, int n_in,
                              void* d_out, int out_size) {
    const float* X     = (const float*)d_in[0];
    const float* mu    = (const float*)d_in[1];
    const float* kappa = (const float*)d_in[2];
    const float* pi    = (const float*)d_in[3];

    int Nrows  = in_sizes[0] / PP;
    int ntiles = (Nrows + TILE_M - 1) / TILE_M;
    int nb     = ntiles < MAX_BLOCKS ? ntiles : MAX_BLOCKS;

    prep_kernel<<<1, 256>>>(mu, kappa, pi);

    size_t smem = (size_t)(TILE_M * XSTRIDE + KK * MSTRIDE) * sizeof(__nv_bfloat16)
                + (size_t)(KK + KK + 8) * sizeof(float);
    cudaFuncSetAttribute(watson_main_kernel,
                         cudaFuncAttributeMaxDynamicSharedMemorySize, (int)smem);
    watson_main_kernel<<<nb, 256, smem>>>(X, Nrows, ntiles);

    reduce_kernel<<<1, 256>>>((float*)d_out, nb);
}

// round 14
// speedup vs baseline: 1.0373x; 1.0373x over previous
#include <cuda_runtime.h>
#include <cuda_bf16.h>
#include <math.h>

// Problem constants (fixed by the dataset): P=256, K=64, N derived from in_sizes.
#define PP 256
#define KK 64
#define TILE_M 128          // rows per CTA
#define XSTRIDE 264         // padded bf16 row stride for X tile (bank-conflict-free)
#define MSTRIDE 264         // padded bf16 row stride for mu tile
#define MAX_BLOCKS 8192

__device__ float         g_kap[KK];
__device__ float         g_w[KK];
__device__ __nv_bfloat16 g_mub[KK * PP];     // [k][p], p contiguous
__device__ float         g_partial[MAX_BLOCKS];
__device__ unsigned      g_done = 0;         // self-re-arming completion counter

// ---------------------------------------------------------------------------
// Preprocess: parallel norms, linear-space Kummer series (no per-iter
// transcendentals), log-softmax(pi), coalesced-read bf16 mu_unit transpose.
// ---------------------------------------------------------------------------
__global__ void prep_kernel(const float* __restrict__ mu,
                            const float* __restrict__ kappa,
                            const float* __restrict__ pi) {
    __shared__ float  srn[KK];
    __shared__ double s_lse_pi;
    const int tid  = threadIdx.x;
    const int warp = tid >> 5;
    const int lane = tid & 31;

    // --- Phase 1: column norms, one warp per 8 components --------------------
    for (int j = 0; j < 8; j++) {
        int k = warp * 8 + j;
        double s = 0.0;
#pragma unroll
        for (int pb = 0; pb < 8; pb++) {
            double v = (double)mu[(pb * 32 + lane) * KK + k];
            s += v * v;
        }
#pragma unroll
        for (int off = 16; off > 0; off >>= 1)
            s += __shfl_down_sync(0xffffffffu, s, off);
        if (lane == 0) srn[k] = (float)(1.0 / sqrt(s));
    }

    // --- Phase 2: softplus + linear-space Kummer (t < 64) --------------------
    double logC = 0.0;
    if (tid < KK) {
        double x = (double)kappa[tid];
        double kap = (x > 0.0) ? x + log1p(exp(-x)) : log1p(exp(x));
        g_kap[tid] = (float)kap;

        // M(0.5, 128, kap) = 1 + sum_j term_j, term_j = term_{j-1}*(j-0.5)/(j*(127+j))*kap
        double term = 1.0, sum = 1.0;
        for (int j = 1; j <= 120; j++) {
            double jd = (double)j;
            term *= (jd - 0.5) / (jd * (127.0 + jd)) * kap;
            sum += term;
            if (term < 1e-17 * sum) break;
        }
        double logkum = log(sum);
        double logSA = lgamma(128.0) - log(2.0) - 128.0 * log(M_PI);
        logC = logSA - logkum;
    }
    if (tid == 0) {
        double m = -1e300;
        for (int k = 0; k < KK; k++) m = fmax(m, (double)pi[k]);
        double s = 0.0;
        for (int k = 0; k < KK; k++) s += exp((double)pi[k] - m);
        s_lse_pi = m + log(s);
    }
    __syncthreads();
    if (tid < KK) g_w[tid] = (float)(logC + (double)pi[tid] - s_lse_pi);

    // --- Phase 3: mu_unit -> bf16 transpose (coalesced reads) ----------------
    for (int i = tid; i < KK * PP; i += blockDim.x) {
        int p = i >> 6;        // mu row
        int k = i & 63;        // mu col (consecutive lanes -> consecutive addrs)
        g_mub[k * PP + p] = __float2bfloat16(mu[i] * srn[k]);
    }
}

// ---------------------------------------------------------------------------
// Main: 128-row tile GEMM (bf16 HMMA) + fused logsumexp epilogue
//       + fused deterministic final reduction (last-block-done).
// X tile staging is WARP-PRIVATE: warp w loads/uses only rows [16w,16w+16),
// so no block barrier is needed around the X load — warps de-phase freely.
// ---------------------------------------------------------------------------
__global__ void __launch_bounds__(256) watson_main_kernel(
        const float* __restrict__ X, float* __restrict__ out,
        int Nrows, int ntiles) {
    extern __shared__ unsigned char smem_raw[];
    __nv_bfloat16* Xs = (__nv_bfloat16*)smem_raw;                 // 128 x 264
    __nv_bfloat16* Ms = Xs + TILE_M * XSTRIDE;                    // 64 x 264
    float* ws   = (float*)(Ms + KK * MSTRIDE);                    // 64
    float* ks   = ws + KK;                                        // 64
    float* wsum = ks + KK;                                        // 8

    __shared__ int s_last;
    const int tid = threadIdx.x;

    // stage mu (bf16), w, kap  (once per CTA)
    for (int i = tid; i < KK * PP; i += 256) {
        Ms[(i >> 8) * MSTRIDE + (i & 255)] = g_mub[i];
    }
    if (tid < KK) { ws[tid] = g_w[tid]; ks[tid] = g_kap[tid]; }
    __syncthreads();   // Ms/ws/ks visible to all warps; only block barrier pre-loop

    const int warp = tid >> 5;
    const int lane = tid & 31;
    const int g = lane >> 2;   // groupID (row within 8)
    const int q = lane & 3;    // thread-in-group

    float block_acc = 0.f;

    for (int tile = blockIdx.x; tile < ntiles; tile += gridDim.x) {
        const long tile0 = (long)tile * TILE_M;
        const float4* X4 = (const float4*)X;
        const bool full_tile = (tile0 + TILE_M) <= (long)Nrows;
        const int r0 = warp * 16;   // this warp's private 16 rows

        // ---- warp-private X staging: 16 rows x 64 float4 = 32 float4/lane ----
        if (full_tile) {
#pragma unroll 4
            for (int j = 0; j < 32; j++) {
                int idx = j * 32 + lane;         // 0..1023
                int r   = r0 + (idx >> 6);       // row within warp's 16
                int c4  = idx & 63;
                float4 v = X4[(tile0 + r) * (PP / 4) + c4];
                __nv_bfloat162* dst = (__nv_bfloat162*)(Xs + r * XSTRIDE + c4 * 4);
                dst[0] = __floats2bfloat162_rn(v.x, v.y);
                dst[1] = __floats2bfloat162_rn(v.z, v.w);
            }
        } else {
            for (int j = 0; j < 32; j++) {
                int idx = j * 32 + lane;
                int r   = r0 + (idx >> 6);
                int c4  = idx & 63;
                long grow = tile0 + r;
                float4 v = make_float4(0.f, 0.f, 0.f, 0.f);
                if (grow < (long)Nrows) v = X4[grow * (PP / 4) + c4];
                __nv_bfloat162* dst = (__nv_bfloat162*)(Xs + r * XSTRIDE + c4 * 4);
                dst[0] = __floats2bfloat162_rn(v.x, v.y);
                dst[1] = __floats2bfloat162_rn(v.z, v.w);
            }
        }
        __syncwarp();   // warp-private rows: STS -> ldmatrix ordering

        float acc[8][4];
#pragma unroll
        for (int nb = 0; nb < 8; nb++)
#pragma unroll
            for (int e = 0; e < 4; e++) acc[nb][e] = 0.f;

        // ldmatrix base: lane -> (row = lane%16, 8-col block = lane/16)
        unsigned a_addr0 = (unsigned)__cvta_generic_to_shared(
            Xs + (r0 + (lane & 15)) * XSTRIDE + (lane >> 4) * 8);

#pragma unroll
        for (int ksi = 0; ksi < 16; ksi++) {
            unsigned a_addr = a_addr0 + (unsigned)(ksi * 16 * 2);
            unsigned a0, a1, a2, a3;
            asm volatile(
                "ldmatrix.sync.aligned.m8n8.x4.shared.b16 {%0,%1,%2,%3}, [%4];"
                : "=r"(a0), "=r"(a1), "=r"(a2), "=r"(a3) : "r"(a_addr));

#pragma unroll
            for (int nb = 0; nb < 8; nb++) {
                const __nv_bfloat16* bp = Ms + (nb * 8 + g) * MSTRIDE + ksi * 16 + 2 * q;
                unsigned b0 = *(const unsigned*)bp;
                unsigned b1 = *(const unsigned*)(bp + 8);
                asm volatile(
                    "mma.sync.aligned.m16n8k16.row.col.f32.bf16.bf16.f32 "
                    "{%0,%1,%2,%3}, {%4,%5,%6,%7}, {%8,%9}, {%0,%1,%2,%3};"
                    : "+f"(acc[nb][0]), "+f"(acc[nb][1]),
                      "+f"(acc[nb][2]), "+f"(acc[nb][3])
                    : "r"(a0), "r"(a1), "r"(a2), "r"(a3), "r"(b0), "r"(b1));
            }
        }

        // Epilogue: density = w[k] + kap[k]*proj^2 ; logsumexp over K per row.
        float rowsum = 0.f;
#pragma unroll
        for (int rh = 0; rh < 2; rh++) {
            long grow = tile0 + r0 + g + rh * 8;
            float d[16];
            float m = -INFINITY;
#pragma unroll
            for (int nb = 0; nb < 8; nb++) {
#pragma unroll
                for (int e = 0; e < 2; e++) {
                    int comp = nb * 8 + 2 * q + e;
                    float pr = acc[nb][rh * 2 + e];
                    float dv = ws[comp] + ks[comp] * pr * pr;
                    d[nb * 2 + e] = dv;
                    m = fmaxf(m, dv);
                }
            }
            m = fmaxf(m, __shfl_xor_sync(0xffffffffu, m, 1));
            m = fmaxf(m, __shfl_xor_sync(0xffffffffu, m, 2));
            float s = 0.f;
#pragma unroll
            for (int i = 0; i < 16; i++) s += expf(d[i] - m);
            s += __shfl_xor_sync(0xffffffffu, s, 1);
            s += __shfl_xor_sync(0xffffffffu, s, 2);
            float L = m + logf(s);
            if (q == 0 && grow < (long)Nrows) rowsum += L;
        }

        // warp reduction, accumulate per-warp into per-CTA via smem
#pragma unroll
        for (int off = 16; off > 0; off >>= 1)
            rowsum += __shfl_xor_sync(0xffffffffu, rowsum, off);
        if (lane == 0) wsum[warp] = rowsum;
        __syncthreads();
        if (tid == 0) {
            float t = 0.f;
            for (int w = 0; w < 8; w++) t += wsum[w];
            block_acc += t;
        }
        __syncthreads();   // wsum reusable next iteration
    }

    // ---- fused deterministic final reduction (last CTA to finish) ----------
    if (tid == 0) {
        g_partial[blockIdx.x] = block_acc;
        __threadfence();
        unsigned t = atomicAdd(&g_done, 1u);
        s_last = (t == (unsigned)gridDim.x - 1u) ? 1 : 0;
    }
    __syncthreads();
    if (s_last) {
        double* sd = (double*)smem_raw;   // main-loop smem no longer needed
        double s = 0.0;
        for (int i = tid; i < gridDim.x; i += 256) s += (double)g_partial[i];
        sd[tid] = s;
        __syncthreads();
        for (int off = 128; off > 0; off >>= 1) {
            if (tid < off) sd[tid] += sd[tid + off];
            __syncthreads();
        }
        if (tid == 0) {
            out[0] = (float)sd[0];
            g_done = 0;                   // re-arm for next graph replay
        }
    }
}

// ---------------------------------------------------------------------------
extern "C" void kernel_launch(void* const* d_in, const int* in_sizes, int n_in,
                              void* d_out, int out_size) {
    const float* X     = (const float*)d_in[0];
    const float* mu    = (const float*)d_in[1];
    const float* kappa = (const float*)d_in[2];
    const float* pi    = (const float*)d_in[3];

    int Nrows  = in_sizes[0] / PP;
    int ntiles = (Nrows + TILE_M - 1) / TILE_M;
    int nb     = ntiles < MAX_BLOCKS ? ntiles : MAX_BLOCKS;

    prep_kernel<<<1, 256>>>(mu, kappa, pi);

    size_t smem = (size_t)(TILE_M * XSTRIDE + KK * MSTRIDE) * sizeof(__nv_bfloat16)
                + (size_t)(KK + KK + 8) * sizeof(float);
    cudaFuncSetAttribute(watson_main_kernel,
                         cudaFuncAttributeMaxDynamicSharedMemorySize, (int)smem);
    watson_main_kernel<<<nb, 256, smem>>>(X, (float*)d_out, Nrows, ntiles);
}